// round 1
// baseline (speedup 1.0000x reference)
#include <cuda_runtime.h>
#include <math.h>

#define N_VARS 64
#define NV1    65      // N = n_vars + 1
#define M_CL   256
#define KD     12
#define CST    68      // padded C row stride in floats (16B aligned)

// Gram matrix C = Sw^T Sw, padded rows (cols 65..67 zero)
__device__ __align__(16) float g_C[NV1 * CST];

// ---------------------------------------------------------------------------
// Kernel 1: C[i][j] = sum_m (S[m,i]*w[m]) * (S[m,j]*w[m])
// ---------------------------------------------------------------------------
__global__ void gram_kernel(const float* __restrict__ S, const float* __restrict__ w)
{
    const int i = blockIdx.x;    // 0..64
    const int j = threadIdx.x;   // 0..67
    float acc = 0.f;
    if (j < NV1) {
#pragma unroll 8
        for (int m = 0; m < M_CL; ++m) {
            const float wm = w[m];
            acc = fmaf(S[m * NV1 + i] * wm, S[m * NV1 + j] * wm, acc);
        }
    }
    g_C[i * CST + j] = (j < NV1) ? acc : 0.f;
}

// ---------------------------------------------------------------------------
// Kernel 2: coordinate-descent mixing. One warp per batch element.
// Lane layout: lane = h*16 + k, k in [0,12) active, h in {0,1}.
//   lane (h,k) holds V[k][n] for n = 32h + j, j = 0..32 (registers).
//   h=0 slot j=32 (n=32) is a permanent zero (owner is h=1, j=0).
// Per step i: g[k] = sum_n C[i][n] V[k][n] - C[i][i] V[k][i];
//             v = -g / max(||g||, 1e-8);  V[k][i] = v.
// ---------------------------------------------------------------------------
__global__ void __launch_bounds__(128)
mix_kernel(const float* __restrict__ z, const float* __restrict__ r,
           const int* __restrict__ miter_p, float* __restrict__ out, int B)
{
    __shared__ __align__(16) float Csh[NV1 * CST];   // 17,680 B
    {
        const float4* src = (const float4*)g_C;
        float4* dst = (float4*)Csh;
#pragma unroll 4
        for (int t = threadIdx.x; t < (NV1 * CST) / 4; t += 128) dst[t] = src[t];
    }
    __syncthreads();

    const int lane = threadIdx.x & 31;
    const int warp = threadIdx.x >> 5;
    const int b    = blockIdx.x * 4 + warp;
    if (b >= B) return;

    const int k = lane & 15;      // component index (0..11 active)
    const int h = lane >> 4;      // which half of n-range
    const unsigned FULL = 0xffffffffu;
    const float PI = 3.14159265358979323846f;

    const int miter = miter_p ? *miter_p : 12;

    float V[33];

    // ---- init: V[0]=e0; V[n] = -cos(pi z)e0 + sin(pi z) r_perp_hat ----
#pragma unroll
    for (int j = 0; j < 33; ++j) {
        const int n  = 32 * h + j;
        const int nc = (n < 1) ? 1 : ((n > 64) ? 64 : n);
        const float zv = z[b * N_VARS + nc - 1];
        const float rv = r[(b * N_VARS + nc - 1) * KD + ((k < KD) ? k : 0)];
        const float rp = (k >= 1 && k < KD) ? rv : 0.f;   // component 0 zeroed
        float s = rp * rp;                                 // ||r_perp||^2 over k
        s += __shfl_xor_sync(FULL, s, 8);
        s += __shfl_xor_sync(FULL, s, 4);
        s += __shfl_xor_sync(FULL, s, 2);
        s += __shfl_xor_sync(FULL, s, 1);
        const float inv = (s > 1e-16f) ? rsqrtf(s) : 1e8f; // 1/max(||r||,eps)
        float sn, cs;
        __sincosf(PI * zv, &sn, &cs);
        float v = sn * (rp * inv);
        if (k == 0) v -= cs;
        const bool valid = (n >= 1) && !(h == 0 && j == 32);
        const float v0 = (k == 0) ? 1.f : 0.f;             // truth vector e0
        V[j] = valid ? v : ((n == 0) ? v0 : 0.f);
    }

    // ---- sweeps ----
    for (int it = 0; it < miter; ++it) {
#pragma unroll
        for (int i = 1; i < NV1; ++i) {
            const int hi = (i < 32) ? 0 : 1;      // owning half of coord i
            const int ji = i - 32 * hi;           // register slot in owner

            const float4* Crow = (const float4*)(Csh + i * CST + 32 * h);
            float a0 = 0.f, a1 = 0.f, a2 = 0.f, a3 = 0.f;
#pragma unroll
            for (int c = 0; c < 8; ++c) {
                const float4 cv = Crow[c];
                a0 = fmaf(cv.x, V[4 * c + 0], a0);
                a1 = fmaf(cv.y, V[4 * c + 1], a1);
                a2 = fmaf(cv.z, V[4 * c + 2], a2);
                a3 = fmaf(cv.w, V[4 * c + 3], a3);
            }
            a0 = fmaf(Csh[i * CST + 32 * h + 32], V[32], a0);  // leftover j=32
            const float acc = (a0 + a1) + (a2 + a3);

            // combine the two n-halves: lane (0,k) <-> lane (1,k)
            float g = acc + __shfl_xor_sync(FULL, acc, 16);

            // remove the n==i self term: g -= C[i][i] * V[k][i]
            const float Cii  = Csh[i * CST + i];
            const float vold = __shfl_sync(FULL, V[ji], (lane & 15) + 16 * hi);
            g = fmaf(-Cii, vold, g);

            // ||g|| over k (idle lanes k>=12 carry g==0)
            float s = g * g;
            s += __shfl_xor_sync(FULL, s, 8);
            s += __shfl_xor_sync(FULL, s, 4);
            s += __shfl_xor_sync(FULL, s, 2);
            s += __shfl_xor_sync(FULL, s, 1);
            const float inv = (s > 1e-16f) ? rsqrtf(s) : 1e8f;
            const float v = -g * inv;

            if (h == hi) V[ji] = v;               // compile-time slot
        }
    }

    // ---- output: out[b][n-1] = acos(clip(-V[0][n])) / pi ----
    if (k == 0) {
#pragma unroll
        for (int j = 0; j < 33; ++j) {
            const int n = 32 * h + j;
            const bool ok = (h == 1) || (j >= 1 && j <= 31);
            if (ok) {
                float c = -V[j];
                c = fminf(fmaxf(c, -1.f + 1e-6f), 1.f - 1e-6f);
                out[b * N_VARS + (n - 1)] = acosf(c) * (1.0f / PI);
            }
        }
    }
}

// ---------------------------------------------------------------------------
extern "C" void kernel_launch(void* const* d_in, const int* in_sizes, int n_in,
                              void* d_out, int out_size)
{
    const float* z = (const float*)d_in[0];
    const float* S = (const float*)d_in[1];
    const float* w = (const float*)d_in[2];
    const float* r = (const float*)d_in[3];
    const int* mi  = (n_in > 4) ? (const int*)d_in[4] : nullptr;
    float* out = (float*)d_out;

    const int B = in_sizes[0] / N_VARS;

    gram_kernel<<<NV1, CST>>>(S, w);
    mix_kernel<<<(B + 3) / 4, 128>>>(z, r, mi, out, B);
}

// round 3
// speedup vs baseline: 1.3271x; 1.3271x over previous
#include <cuda_runtime.h>
#include <math.h>

#define N_VARS 64
#define NV1    65      // N = n_vars + 1
#define M_CL   256
#define KD     12
#define CST    68      // padded C row stride in floats (16B aligned)

// Gram matrix C = Sw^T Sw with ZEROED DIAGONAL, padded rows (cols 65..67 zero)
__device__ __align__(16) float g_C[NV1 * CST];

// ---------------------------------------------------------------------------
// Kernel 1: C[i][j] = sum_m (S[m,i]*w[m]) * (S[m,j]*w[m]);  C[i][i] forced to 0
// ---------------------------------------------------------------------------
__global__ void gram_kernel(const float* __restrict__ S, const float* __restrict__ w)
{
    const int i = blockIdx.x;    // 0..64
    const int j = threadIdx.x;   // 0..67
    float acc = 0.f;
    if (j < NV1) {
#pragma unroll 16
        for (int m = 0; m < M_CL; ++m) {
            const float wm = __ldg(&w[m]);
            acc = fmaf(__ldg(&S[m * NV1 + i]) * wm, __ldg(&S[m * NV1 + j]) * wm, acc);
        }
    }
    g_C[i * CST + j] = (j < NV1 && j != i) ? acc : 0.f;
}

// ---------------------------------------------------------------------------
// Kernel 2: software-pipelined coordinate descent. One warp per batch element.
// Lane layout: lane = h*16 + k, k in [0,12) active, h in {0,1}.
//   lane (h,k) holds V[k][n] for n = 32h + j, j = 0..32 (registers).
// Recurrence: g_i = P_i + C[i,i-1]*v_{i-1},
//   P_i = sum_{n != i-1} C[i,n] V[n]   (precomputed off the critical chain)
//   v_{i-1} = -g_{i-1} * inv_{i-1}  =>  g_i = fma(-C*g_{i-1}, inv_{i-1}, P_i)
// ---------------------------------------------------------------------------
__global__ void __launch_bounds__(128)
mix_kernel(const float* __restrict__ z, const float* __restrict__ r,
           const int* __restrict__ miter_p, float* __restrict__ out, int B)
{
    __shared__ __align__(16) float Csh[NV1 * CST];   // 17,680 B
    {
        const float4* src = (const float4*)g_C;
        float4* dst = (float4*)Csh;
#pragma unroll 4
        for (int t = threadIdx.x; t < (NV1 * CST) / 4; t += 128) dst[t] = src[t];
    }
    __syncthreads();

    const int lane = threadIdx.x & 31;
    const int warp = threadIdx.x >> 5;
    const int b    = blockIdx.x * 4 + warp;
    if (b >= B) return;

    const int k = lane & 15;      // component index (0..11 active)
    const int h = lane >> 4;      // which half of n-range
    const unsigned FULL = 0xffffffffu;
    const float PI = 3.14159265358979323846f;

    const int miter = miter_p ? *miter_p : 12;

    float V[33];

    // ---- init: V[0]=e0; V[n] = -cos(pi z)e0 + sin(pi z) r_perp_hat ----
#pragma unroll
    for (int j = 0; j < 33; ++j) {
        const int n  = 32 * h + j;
        const int nc = (n < 1) ? 1 : ((n > 64) ? 64 : n);
        const float zv = z[b * N_VARS + nc - 1];
        const float rv = r[(b * N_VARS + nc - 1) * KD + ((k < KD) ? k : 0)];
        const float rp = (k >= 1 && k < KD) ? rv : 0.f;   // component 0 zeroed
        float s = rp * rp;                                 // ||r_perp||^2 over k
        s += __shfl_xor_sync(FULL, s, 8);
        s += __shfl_xor_sync(FULL, s, 4);
        s += __shfl_xor_sync(FULL, s, 2);
        s += __shfl_xor_sync(FULL, s, 1);
        const float inv0 = (s > 1e-16f) ? rsqrtf(s) : 1e8f; // 1/max(||r||,eps)
        float sn, cs;
        __sincosf(PI * zv, &sn, &cs);
        float v = sn * (rp * inv0);
        if (k == 0) v -= cs;
        const bool valid = (n >= 1) && !(h == 0 && j == 32);
        const float v0 = (k == 0) ? 1.f : 0.f;             // truth vector e0
        V[j] = valid ? v : ((n == 0) ? v0 : 0.f);
    }

    // ---- pipelined sweeps ----
    float P, t = 0.f, inv = 0.f;

    // prologue: P = combined full dot of row 1 (no pending coordinate)
    {
        const float4* Crow = (const float4*)(Csh + 1 * CST + 32 * h);
        float a0 = 0.f, a1 = 0.f, a2 = 0.f, a3 = 0.f;
#pragma unroll
        for (int c = 0; c < 8; ++c) {
            const float4 cv = Crow[c];
            a0 = fmaf(cv.x, V[4 * c + 0], a0);
            a1 = fmaf(cv.y, V[4 * c + 1], a1);
            a2 = fmaf(cv.z, V[4 * c + 2], a2);
            a3 = fmaf(cv.w, V[4 * c + 3], a3);
        }
        const float a4 = Csh[1 * CST + 32 * h + 32] * V[32];
        const float acc = ((a0 + a1) + (a2 + a3)) + a4;
        P = acc + __shfl_xor_sync(FULL, acc, 16);
    }

    for (int it = 0; it < miter; ++it) {
#pragma unroll
        for (int i = 1; i < NV1; ++i) {
            const int hi = (i < 32) ? 0 : 1;      // owning half of coord i
            const int ji = i - 32 * hi;           // register slot in owner
            const int inext = (i < 64) ? i + 1 : 1;

            // -------- critical chain: g, ||g||^2, inv --------
            const float g = fmaf(t, inv, P);

            // two-level parallel-shuffle reduction over the 16-lane half
            const float c1 = __shfl_xor_sync(FULL, g, 4);
            const float c2 = __shfl_xor_sync(FULL, g, 8);
            const float c3 = __shfl_xor_sync(FULL, g, 12);
            float s4 = g * g;
            s4 = fmaf(c1, c1, s4);
            s4 = fmaf(c2, c2, s4);
            s4 = fmaf(c3, c3, s4);
            const float d1 = __shfl_xor_sync(FULL, s4, 1);
            const float d2 = __shfl_xor_sync(FULL, s4, 2);
            const float d3 = __shfl_xor_sync(FULL, s4, 3);
            float s = (s4 + d1) + (d2 + d3);
            s = fmaxf(s, 1e-16f);

            // -------- off-chain: precompute next row while shuffles fly -----
            const float cni = Csh[inext * CST + i];   // C[inext][i]
            t = -cni * g;                             // pending-term coeff

            const float4* Crow = (const float4*)(Csh + inext * CST + 32 * h);
            float a0 = 0.f, a1 = 0.f, a2 = 0.f, a3 = 0.f;
#pragma unroll
            for (int c = 0; c < 8; ++c) {
                const float4 cv = Crow[c];
                a0 = fmaf(cv.x, V[4 * c + 0], a0);
                a1 = fmaf(cv.y, V[4 * c + 1], a1);
                a2 = fmaf(cv.z, V[4 * c + 2], a2);
                a3 = fmaf(cv.w, V[4 * c + 3], a3);
            }
            const float a4 = Csh[inext * CST + 32 * h + 32] * V[32];
            float acc = ((a0 + a1) + (a2 + a3)) + a4;
            if (h == hi) acc = fmaf(-cni, V[ji], acc);    // remove OLD V[i] term
            P = acc + __shfl_xor_sync(FULL, acc, 16);

            // -------- finish chain, commit v_i --------
            inv = rsqrtf(s);
            const float v = -g * inv;
            if (h == hi) V[ji] = v;                       // overwrite AFTER removal
        }
    }

    // ---- output: out[b][n-1] = acos(clip(-V[0][n])) / pi ----
    if (k == 0) {
#pragma unroll
        for (int j = 0; j < 33; ++j) {
            const int n = 32 * h + j;
            const bool ok = (h == 1) || (j >= 1 && j <= 31);
            if (ok) {
                float c = -V[j];
                c = fminf(fmaxf(c, -1.f + 1e-6f), 1.f - 1e-6f);
                out[b * N_VARS + (n - 1)] = acosf(c) * (1.0f / PI);
            }
        }
    }
}

// ---------------------------------------------------------------------------
extern "C" void kernel_launch(void* const* d_in, const int* in_sizes, int n_in,
                              void* d_out, int out_size)
{
    const float* z = (const float*)d_in[0];
    const float* S = (const float*)d_in[1];
    const float* w = (const float*)d_in[2];
    const float* r = (const float*)d_in[3];
    const int* mi  = (n_in > 4) ? (const int*)d_in[4] : nullptr;
    float* out = (float*)d_out;

    const int B = in_sizes[0] / N_VARS;

    gram_kernel<<<NV1, CST>>>(S, w);
    mix_kernel<<<(B + 3) / 4, 128>>>(z, r, mi, out, B);
}